// round 1
// baseline (speedup 1.0000x reference)
#include <cuda_runtime.h>
#include <math.h>

#define Nn   131072
#define Bg   512
#define NPG  256
#define PSDm 512
#define RDm  64
#define Rr   51

// ---------------- device scratch (no allocations allowed) ----------------
__device__ float g_tables[5][Rr][128];   // folded label tables (+bias)
__device__ float g_PG[2][Bg][128];       // per-graph hb/tb contributions (C, E)
__device__ float g_gsum[Bg][3][PSDm];    // g_out, ghs, gts (already divided)
__device__ float g_ght[Bg][3200];
__device__ float g_htout[Bg][PSDm];

// ---------------- kernel 1: label tables -------------------------------
// t0: rel_emb @ A_w[512:576] + A_b
// t1: she @ C_w[1536:1600]          t2: she @ C_w[1600:1664] + C_b
// t3: ste @ E_w[1536:1600]          t4: ste @ E_w[1600:1664] + E_b
__global__ void k_tables(const float* __restrict__ rel_emb,
                         const float* __restrict__ she,
                         const float* __restrict__ ste,
                         const float* __restrict__ A_w, const float* __restrict__ A_b,
                         const float* __restrict__ C_w, const float* __restrict__ C_b,
                         const float* __restrict__ E_w, const float* __restrict__ E_b)
{
    int r = blockIdx.x;      // 0..50
    int t = blockIdx.y;      // 0..4
    int d = threadIdx.x;     // 0..127
    const float* emb; const float* W; const float* bias = 0;
    switch (t) {
        case 0: emb = rel_emb; W = A_w + 512*128;  bias = A_b; break;
        case 1: emb = she;     W = C_w + 1536*128;             break;
        case 2: emb = she;     W = C_w + 1600*128; bias = C_b; break;
        case 3: emb = ste;     W = E_w + 1536*128;             break;
        default:emb = ste;     W = E_w + 1600*128; bias = E_b; break;
    }
    float acc = bias ? bias[d] : 0.f;
    for (int k = 0; k < 64; k++) acc += emb[r*64 + k] * W[k*128 + d];
    g_tables[t][r][d] = acc;
}

// ---------------- kernel 2: per-graph PG terms --------------------------
// path 0: PG_C = hN@C_w[512:1024] + tN@C_w[1024:1536]
// path 1: PG_E = tN@E_w[512:1024] + hN@E_w[1024:1536]
__global__ void k_pg(const float* __restrict__ flat,
                     const int* __restrict__ head_ids, const int* __restrict__ tail_ids,
                     const float* __restrict__ C_w, const float* __restrict__ E_w)
{
    int path = blockIdx.z;
    const float* W = (path == 0 ? C_w : E_w) + 512*128;
    int m0 = blockIdx.y * 32, n0 = blockIdx.x * 32;
    __shared__ float As[32][33], Bs[32][33];
    __shared__ int rowA[32], rowB[32];
    int tid = threadIdx.x;
    if (tid < 32) {
        int g = m0 + tid;
        int h = head_ids[g], t = tail_ids[g];
        rowA[tid] = (path == 0) ? h : t;
        rowB[tid] = (path == 0) ? t : h;
    }
    __syncthreads();
    int tx = tid & 15, ty = tid >> 4;
    float acc[2][2] = {{0.f,0.f},{0.f,0.f}};
    for (int k0 = 0; k0 < 1024; k0 += 32) {
        for (int e = tid; e < 1024; e += 256) {
            int m = e >> 5, k = e & 31;
            int kg = k0 + k;
            int row = (kg < 512) ? rowA[m] : rowB[m];
            int kk  = (kg < 512) ? kg : kg - 512;
            As[m][k] = flat[(size_t)row*512 + kk];
        }
        for (int e = tid; e < 1024; e += 256) {
            int k = e >> 5, n = e & 31;
            Bs[k][n] = W[(size_t)(k0 + k)*128 + n0 + n];
        }
        __syncthreads();
        #pragma unroll
        for (int k = 0; k < 32; k++) {
            float a0 = As[ty*2][k], a1 = As[ty*2+1][k];
            float b0 = Bs[k][tx*2], b1 = Bs[k][tx*2+1];
            acc[0][0] += a0*b0; acc[0][1] += a0*b1;
            acc[1][0] += a1*b0; acc[1][1] += a1*b1;
        }
        __syncthreads();
    }
    #pragma unroll
    for (int i = 0; i < 2; i++)
        #pragma unroll
        for (int q = 0; q < 2; q++)
            g_PG[path][m0 + ty*2 + i][n0 + tx*2 + q] = acc[i][q];
}

// ---------------- kernel 3: fused per-node GEMM + gates + segment means --
// One block per graph. 2 M-tiles of 128 nodes; 3 N-chunks (A/C/E paths).
__global__ __launch_bounds__(256, 2) void k_fused(
    const float* __restrict__ flat,
    const float* __restrict__ head_sister, const float* __restrict__ tail_sister,
    const int* __restrict__ t_label, const int* __restrict__ hst, const int* __restrict__ tst,
    const float* __restrict__ A_w, const float* __restrict__ C_w, const float* __restrict__ E_w,
    const float* __restrict__ B_w, const float* __restrict__ B_b,
    const float* __restrict__ Dm_w, const float* __restrict__ Dm_b,
    const float* __restrict__ G_w, const float* __restrict__ G_b)
{
    extern __shared__ __align__(16) float sm[];
    float* uAs    = sm;                   // [128][33]  (union w/ Hs)
    float* uBs    = sm + 4224;            // [32][132]
    float* Hs     = sm;                   // [128][129] (union)
    float* Wsm    = sm + 16512;           // [3][128][4]
    float* numAcc = Wsm + 1536;           // [3][512]
    float* denAcc = numAcc + 1536;        // [12]
    float* SW     = denAcc + 12;          // [3][128][4]
    float* SB     = SW + 1536;            // [12]
    float* PGs    = SB + 12;              // [2][128]
    int*   lbl    = (int*)(PGs + 256);    // [3][128]

    const int b   = blockIdx.x;
    const int tid = threadIdx.x;
    const int tx  = tid & 15, ty = tid >> 4;

    for (int i = tid; i < 512; i += 256) {
        SW[0*512 + i] = B_w[i];
        SW[1*512 + i] = Dm_w[i];
        SW[2*512 + i] = G_w[i];
    }
    if (tid < 12) {
        int p = tid >> 2, l = tid & 3;
        SB[tid] = (p == 0) ? B_b[l] : ((p == 1) ? Dm_b[l] : G_b[l]);
        denAcc[tid] = 0.f;
    }
    if (tid < 256) PGs[tid] = g_PG[tid >> 7][b][tid & 127];
    for (int i = tid; i < 1536; i += 256) numAcc[i] = 0.f;
    __syncthreads();

    for (int mt = 0; mt < 2; mt++) {
        const int rowbase = b*NPG + mt*128;
        if (tid < 128) {
            lbl[tid]       = t_label[rowbase + tid];
            lbl[128 + tid] = hst[rowbase + tid];
            lbl[256 + tid] = tst[rowbase + tid];
        }
        __syncthreads();

        for (int j = 0; j < 3; j++) {
            const float* W = (j == 0) ? A_w : ((j == 1) ? C_w : E_w);
            float acc[8][8];
            #pragma unroll
            for (int i = 0; i < 8; i++)
                #pragma unroll
                for (int q = 0; q < 8; q++) acc[i][q] = 0.f;

            for (int k0 = 0; k0 < 512; k0 += 32) {
                #pragma unroll
                for (int r = 0; r < 16; r++) {
                    int e = r*256 + tid;
                    int m = e >> 5, k = e & 31;
                    uAs[m*33 + k] = flat[(size_t)(rowbase + m)*512 + k0 + k];
                }
                #pragma unroll
                for (int r = 0; r < 16; r++) {
                    int e = r*256 + tid;
                    int k = e >> 7, n = e & 127;
                    uBs[k*132 + n] = W[(size_t)(k0 + k)*128 + n];
                }
                __syncthreads();
                #pragma unroll
                for (int k = 0; k < 32; k++) {
                    float a[8];
                    #pragma unroll
                    for (int i = 0; i < 8; i++) a[i] = uAs[(ty*8 + i)*33 + k];
                    float4 b0 = *(const float4*)&uBs[k*132 + tx*4];
                    float4 b1 = *(const float4*)&uBs[k*132 + 64 + tx*4];
                    float bb[8] = {b0.x,b0.y,b0.z,b0.w,b1.x,b1.y,b1.z,b1.w};
                    #pragma unroll
                    for (int i = 0; i < 8; i++)
                        #pragma unroll
                        for (int q = 0; q < 8; q++) acc[i][q] += a[i]*bb[q];
                }
                __syncthreads();
            }
            // epilogue: gathered adds + ReLU -> Hs
            #pragma unroll
            for (int i = 0; i < 8; i++) {
                int m = ty*8 + i;
                int lT = lbl[m], lH = lbl[128 + m], lS = lbl[256 + m];
                #pragma unroll
                for (int q = 0; q < 8; q++) {
                    int c = (q < 4) ? (tx*4 + q) : (64 + tx*4 + q - 4);
                    float v = acc[i][q];
                    if (j == 0)      v += g_tables[0][lT][c];
                    else if (j == 1) v += PGs[c]       + g_tables[1][lH][c] + g_tables[2][lT][c];
                    else             v += PGs[128 + c] + g_tables[3][lS][c] + g_tables[4][lT][c];
                    Hs[m*129 + c] = fmaxf(v, 0.f);
                }
            }
            __syncthreads();
            // [128,4] projection + sigmoid + sister gating -> Wsm
            {
                int n  = tid & 127;
                int l0 = tid >> 7;                 // 0/1; also does l0+2
                float a0 = SB[j*4 + l0], a1 = SB[j*4 + l0 + 2];
                #pragma unroll 4
                for (int d = 0; d < 128; d++) {
                    float h = Hs[n*129 + d];
                    a0 += h * SW[j*512 + d*4 + l0];
                    a1 += h * SW[j*512 + d*4 + l0 + 2];
                }
                float s0 = 1.f / (1.f + expf(-a0));
                float s1 = 1.f / (1.f + expf(-a1));
                if (j == 1) {
                    s0 *= head_sister[(size_t)(rowbase + n)*4 + l0];
                    s1 *= head_sister[(size_t)(rowbase + n)*4 + l0 + 2];
                } else if (j == 2) {
                    s0 *= tail_sister[(size_t)(rowbase + n)*4 + l0];
                    s1 *= tail_sister[(size_t)(rowbase + n)*4 + l0 + 2];
                }
                Wsm[(j*128 + n)*4 + l0]     = s0;
                Wsm[(j*128 + n)*4 + l0 + 2] = s1;
            }
            __syncthreads();
        }

        // weighted segment sums for this M-tile (thread owns cols tid, tid+256)
        {
            int c0 = tid, c1 = tid + 256;
            int l0 = tid >> 7, l1 = l0 + 2;
            float s00=0,s01=0,s02=0, s10=0,s11=0,s12=0;
            for (int n = 0; n < 128; n++) {
                float v0 = flat[(size_t)(rowbase + n)*512 + c0];
                float v1 = flat[(size_t)(rowbase + n)*512 + c1];
                float w0 = Wsm[(0*128+n)*4 + l0], w1 = Wsm[(1*128+n)*4 + l0], w2 = Wsm[(2*128+n)*4 + l0];
                float x0 = Wsm[(0*128+n)*4 + l1], x1 = Wsm[(1*128+n)*4 + l1], x2 = Wsm[(2*128+n)*4 + l1];
                s00 += w0*v0; s01 += w1*v0; s02 += w2*v0;
                s10 += x0*v1; s11 += x1*v1; s12 += x2*v1;
            }
            numAcc[0*512 + c0] += s00; numAcc[1*512 + c0] += s01; numAcc[2*512 + c0] += s02;
            numAcc[0*512 + c1] += s10; numAcc[1*512 + c1] += s11; numAcc[2*512 + c1] += s12;
            if (tid < 12) {
                int p = tid >> 2, l = tid & 3;
                float s = 0.f;
                for (int n = 0; n < 128; n++) s += Wsm[(p*128 + n)*4 + l];
                denAcc[tid] += s;
            }
        }
        __syncthreads();
    }

    // divide and store g_out / ghs / gts
    {
        int c0 = tid, c1 = tid + 256;
        int l0 = tid >> 7, l1 = l0 + 2;
        #pragma unroll
        for (int p = 0; p < 3; p++) {
            g_gsum[b][p][c0] = numAcc[p*512 + c0] / denAcc[p*4 + l0];
            g_gsum[b][p][c1] = numAcc[p*512 + c1] / denAcc[p*4 + l1];
        }
    }
}

// ---------------- kernel 3.5: assemble g_ht rows ------------------------
__global__ void k_ght(const float* __restrict__ flat,
                      const int* __restrict__ head_ids, const int* __restrict__ tail_ids,
                      const int* __restrict__ rel_labels,
                      const float* __restrict__ she, const float* __restrict__ ste)
{
    int b = blockIdx.x, tid = threadIdx.x;
    int h = head_ids[b], t = tail_ids[b];
    float* out = g_ght[b];
    for (int c = tid; c < 512; c += 256) {
        float ghs = g_gsum[b][1][c], gts = g_gsum[b][2][c];
        float hv = flat[(size_t)h*512 + c], tv = flat[(size_t)t*512 + c];
        out[c]        = ghs * hv;
        out[512 + c]  = gts * tv;
        out[1024 + c] = ghs;
        out[1536 + c] = gts;
        out[2048 + c] = hv;
        out[2560 + c] = tv;
    }
    if (tid < 64) {
        int r = rel_labels[b];
        out[3072 + tid] = she[r*64 + tid];
        out[3136 + tid] = ste[r*64 + tid];
    }
}

// ---------------- kernel 4a: ht GEMM [512,3200]@[3200,512] + relu -------
__global__ void k_ht(const float* __restrict__ ht_w, const float* __restrict__ ht_b)
{
    __shared__ float As[32][33], Bs[32][33];
    int m0 = blockIdx.y*32, n0 = blockIdx.x*32;
    int tid = threadIdx.x, tx = tid & 15, ty = tid >> 4;
    float acc[2][2] = {{0.f,0.f},{0.f,0.f}};
    for (int k0 = 0; k0 < 3200; k0 += 32) {
        for (int e = tid; e < 1024; e += 256) { int m = e>>5, k = e&31; As[m][k] = g_ght[m0+m][k0+k]; }
        for (int e = tid; e < 1024; e += 256) { int k = e>>5, n = e&31; Bs[k][n] = ht_w[(size_t)(k0+k)*512 + n0 + n]; }
        __syncthreads();
        #pragma unroll
        for (int k = 0; k < 32; k++) {
            float a0 = As[ty*2][k], a1 = As[ty*2+1][k];
            float b0 = Bs[k][tx*2], b1 = Bs[k][tx*2+1];
            acc[0][0]+=a0*b0; acc[0][1]+=a0*b1; acc[1][0]+=a1*b0; acc[1][1]+=a1*b1;
        }
        __syncthreads();
    }
    #pragma unroll
    for (int i = 0; i < 2; i++)
        #pragma unroll
        for (int q = 0; q < 2; q++) {
            int m = m0 + ty*2 + i, n = n0 + tx*2 + q;
            g_htout[m][n] = fmaxf(acc[i][q] + ht_b[n], 0.f);
        }
}

// ---------------- kernel 4b: fc + out -----------------------------------
__global__ void k_final(const float* __restrict__ flat,
                        const int* __restrict__ head_ids, const int* __restrict__ tail_ids,
                        const int* __restrict__ rel_labels, const float* __restrict__ rel_emb,
                        const float* __restrict__ fc_w, const float* __restrict__ fc_b,
                        const float* __restrict__ out_w, const float* __restrict__ out_b,
                        float* __restrict__ out)
{
    __shared__ float rep[2112];
    __shared__ float red[256][17];
    int b = blockIdx.x, tid = threadIdx.x;
    int h = head_ids[b], t = tail_ids[b];
    for (int c = tid; c < 512; c += 256) {
        rep[c]        = g_gsum[b][0][c];
        rep[512 + c]  = flat[(size_t)h*512 + c];
        rep[1024 + c] = flat[(size_t)t*512 + c];
        rep[1536 + c] = g_htout[b][c];
    }
    if (tid < 64) rep[2048 + tid] = rel_emb[rel_labels[b]*64 + tid];
    __syncthreads();

    float acc[16];
    #pragma unroll
    for (int j = 0; j < 16; j++) acc[j] = 0.f;
    for (int k = tid; k < 2112; k += 256) {
        float x = rep[k];
        const float4* w = (const float4*)(fc_w + (size_t)k*16);
        #pragma unroll
        for (int v = 0; v < 4; v++) {
            float4 ww = w[v];
            acc[v*4+0] += x*ww.x; acc[v*4+1] += x*ww.y; acc[v*4+2] += x*ww.z; acc[v*4+3] += x*ww.w;
        }
    }
    #pragma unroll
    for (int j = 0; j < 16; j++) red[tid][j] = acc[j];
    __syncthreads();
    for (int s = 128; s >= 1; s >>= 1) {
        if (tid < s) {
            #pragma unroll
            for (int j = 0; j < 16; j++) red[tid][j] += red[tid + s][j];
        }
        __syncthreads();
    }
    if (tid == 0) {
        float o = out_b[0];
        #pragma unroll
        for (int j = 0; j < 16; j++) o += fmaxf(red[0][j] + fc_b[j], 0.f) * out_w[j];
        out[b] = o;
    }
}

// ---------------- launch ------------------------------------------------
extern "C" void kernel_launch(void* const* d_in, const int* in_sizes, int n_in,
                              void* d_out, int out_size)
{
    const float* node_repr = (const float*)d_in[0];   // [N, 4, 128] == flat [N,512]
    const float* head_sis  = (const float*)d_in[1];
    const float* tail_sis  = (const float*)d_in[2];
    const int*   t_label   = (const int*)d_in[3];
    const int*   hst       = (const int*)d_in[4];
    const int*   tst       = (const int*)d_in[5];
    // d_in[6] graph_ids (implicit: n/256)
    const int*   head_ids  = (const int*)d_in[7];
    const int*   tail_ids  = (const int*)d_in[8];
    const int*   rel_lab   = (const int*)d_in[9];
    const float* rel_emb   = (const float*)d_in[10];
    const float* she       = (const float*)d_in[11];
    const float* ste       = (const float*)d_in[12];
    const float* A_w  = (const float*)d_in[13]; const float* A_b  = (const float*)d_in[14];
    const float* B_w  = (const float*)d_in[15]; const float* B_b  = (const float*)d_in[16];
    const float* C_w  = (const float*)d_in[17]; const float* C_b  = (const float*)d_in[18];
    const float* Dm_w = (const float*)d_in[19]; const float* Dm_b = (const float*)d_in[20];
    const float* E_w  = (const float*)d_in[21]; const float* E_b  = (const float*)d_in[22];
    const float* G_w  = (const float*)d_in[23]; const float* G_b  = (const float*)d_in[24];
    const float* ht_w = (const float*)d_in[25]; const float* ht_b = (const float*)d_in[26];
    const float* fc_w = (const float*)d_in[27]; const float* fc_b = (const float*)d_in[28];
    const float* out_w= (const float*)d_in[29]; const float* out_b= (const float*)d_in[30];
    float* out = (float*)d_out;

    const int fusedSmem = (16512 + 1536 + 1536 + 12 + 1536 + 12 + 256) * 4 + 384 * 4;
    cudaFuncSetAttribute(k_fused, cudaFuncAttributeMaxDynamicSharedMemorySize, fusedSmem);

    k_tables<<<dim3(Rr, 5), 128>>>(rel_emb, she, ste, A_w, A_b, C_w, C_b, E_w, E_b);
    k_pg<<<dim3(4, 16, 2), 256>>>(node_repr, head_ids, tail_ids, C_w, E_w);
    k_fused<<<Bg, 256, fusedSmem>>>(node_repr, head_sis, tail_sis, t_label, hst, tst,
                                    A_w, C_w, E_w, B_w, B_b, Dm_w, Dm_b, G_w, G_b);
    k_ght<<<Bg, 256>>>(node_repr, head_ids, tail_ids, rel_lab, she, ste);
    k_ht<<<dim3(16, 16), 256>>>(ht_w, ht_b);
    k_final<<<Bg, 256>>>(node_repr, head_ids, tail_ids, rel_lab, rel_emb,
                         fc_w, fc_b, out_w, out_b, out);
}

// round 5
// speedup vs baseline: 1.2667x; 1.2667x over previous
#include <cuda_runtime.h>
#include <math.h>
#include <stdint.h>

#define Bg   512
#define NPG  256
#define Rr   51

// ---------------- device scratch ----------------
__device__ float    g_tables[5][Rr][128];
__device__ float    g_PG[2][Bg][128];
__device__ float    g_gsum[Bg][3][512];
__device__ float    g_ght[Bg][3200];
__device__ float    g_htacc[4][Bg][512];
__device__ uint32_t g_Wt_hi[3 * 128 * 512];    // [path][n][k] tf32 hi, k-permuted
__device__ uint32_t g_Wt_lo[3 * 128 * 512];    // residual lo

__device__ __forceinline__ uint32_t f2tf(float x) {
    uint32_t u; asm("cvt.rna.tf32.f32 %0, %1;" : "=r"(u) : "f"(x)); return u;
}
__device__ __forceinline__ void mma_tf32(float* d, const uint32_t* a, const uint32_t* b) {
    asm volatile(
        "mma.sync.aligned.m16n8k8.row.col.f32.tf32.tf32.f32 "
        "{%0,%1,%2,%3}, {%4,%5,%6,%7}, {%8,%9}, {%0,%1,%2,%3};"
        : "+f"(d[0]), "+f"(d[1]), "+f"(d[2]), "+f"(d[3])
        : "r"(a[0]), "r"(a[1]), "r"(a[2]), "r"(a[3]), "r"(b[0]), "r"(b[1]));
}

// k-permutation within a 32-wide chunk: (c, c+4) pairs become adjacent
__device__ __forceinline__ int kperm(int c) {
    return (c & ~7) + ((c & 3) << 1) + ((c >> 2) & 1);
}

// ---------------- kernel 1: label tables -------------------------------
__global__ void k_tables(const float* __restrict__ rel_emb,
                         const float* __restrict__ she,
                         const float* __restrict__ ste,
                         const float* __restrict__ A_w, const float* __restrict__ A_b,
                         const float* __restrict__ C_w, const float* __restrict__ C_b,
                         const float* __restrict__ E_w, const float* __restrict__ E_b)
{
    int r = blockIdx.x, t = blockIdx.y, d = threadIdx.x;
    const float* emb; const float* W; const float* bias = 0;
    switch (t) {
        case 0: emb = rel_emb; W = A_w + 512*128;  bias = A_b; break;
        case 1: emb = she;     W = C_w + 1536*128;             break;
        case 2: emb = she;     W = C_w + 1600*128; bias = C_b; break;
        case 3: emb = ste;     W = E_w + 1536*128;             break;
        default:emb = ste;     W = E_w + 1600*128; bias = E_b; break;
    }
    float acc = bias ? bias[d] : 0.f;
    for (int k = 0; k < 64; k++) acc += emb[r*64 + k] * W[k*128 + d];
    g_tables[t][r][d] = acc;
}

// ---------------- kernel 1b: transpose + permute + tf32 hi/lo weights ---
__global__ void k_prep(const float* __restrict__ A_w, const float* __restrict__ C_w,
                       const float* __restrict__ E_w)
{
    int c = blockIdx.x;   // K chunk 0..15
    int j = blockIdx.y;   // path 0..2
    const float* W = (j == 0) ? A_w : ((j == 1) ? C_w : E_w);
    for (int e = threadIdx.x; e < 4096; e += 256) {
        int n = e >> 5, kk = e & 31;
        float v = W[(size_t)(c*32 + kk)*128 + n];
        uint32_t hi = f2tf(v);
        uint32_t lo = f2tf(v - __uint_as_float(hi));
        size_t idx = (size_t)(j*128 + n)*512 + c*32 + kperm(kk);
        g_Wt_hi[idx] = hi;
        g_Wt_lo[idx] = lo;
    }
}

// ---------------- kernel 2: per-graph PG terms --------------------------
__global__ void k_pg(const float* __restrict__ flat,
                     const int* __restrict__ head_ids, const int* __restrict__ tail_ids,
                     const float* __restrict__ C_w, const float* __restrict__ E_w)
{
    int path = blockIdx.z;
    const float* W = (path == 0 ? C_w : E_w) + 512*128;
    int m0 = blockIdx.y * 32, n0 = blockIdx.x * 32;
    __shared__ float As[32][33], Bs[32][33];
    __shared__ int rowA[32], rowB[32];
    int tid = threadIdx.x;
    if (tid < 32) {
        int g = m0 + tid;
        int h = head_ids[g], t = tail_ids[g];
        rowA[tid] = (path == 0) ? h : t;
        rowB[tid] = (path == 0) ? t : h;
    }
    __syncthreads();
    int tx = tid & 15, ty = tid >> 4;
    float acc[2][2] = {{0.f,0.f},{0.f,0.f}};
    for (int k0 = 0; k0 < 1024; k0 += 32) {
        for (int e = tid; e < 1024; e += 256) {
            int m = e >> 5, k = e & 31;
            int kg = k0 + k;
            int row = (kg < 512) ? rowA[m] : rowB[m];
            int kk  = (kg < 512) ? kg : kg - 512;
            As[m][k] = flat[(size_t)row*512 + kk];
        }
        for (int e = tid; e < 1024; e += 256) {
            int k = e >> 5, n = e & 31;
            Bs[k][n] = W[(size_t)(k0 + k)*128 + n0 + n];
        }
        __syncthreads();
        #pragma unroll
        for (int k = 0; k < 32; k++) {
            float a0 = As[ty*2][k], a1 = As[ty*2+1][k];
            float b0 = Bs[k][tx*2], b1 = Bs[k][tx*2+1];
            acc[0][0] += a0*b0; acc[0][1] += a0*b1;
            acc[1][0] += a1*b0; acc[1][1] += a1*b1;
        }
        __syncthreads();
    }
    #pragma unroll
    for (int i = 0; i < 2; i++)
        #pragma unroll
        for (int q = 0; q < 2; q++)
            g_PG[path][m0 + ty*2 + i][n0 + tx*2 + q] = acc[i][q];
}

// ---------------- kernel 3: fused per-node pipeline (3xTF32 mma.sync) ---
// smem layout (floats)
#define ASH_OFF  0        // 128*36 = 4608
#define ASL_OFF  4608
#define BTH_OFF  9216
#define BTL_OFF  13824
#define SW_OFF   18432    // 1536
#define SB_OFF   19968    // 16
#define PG_OFF   19984    // 256
#define WSM_OFF  20240    // 1536
#define NUM_OFF  21776    // 1536
#define DEN_OFF  23312    // 16
#define PRJ_OFF  23328    // 512
#define LBL_OFF  23840    // 384 (ints)
#define SM_FLOATS 24224

__global__ __launch_bounds__(256, 2) void k_fused_mma(
    const float* __restrict__ flat,
    const float* __restrict__ head_sister, const float* __restrict__ tail_sister,
    const int* __restrict__ t_label, const int* __restrict__ hst, const int* __restrict__ tst,
    const float* __restrict__ B_w, const float* __restrict__ B_b,
    const float* __restrict__ Dm_w, const float* __restrict__ Dm_b,
    const float* __restrict__ G_w, const float* __restrict__ G_b)
{
    extern __shared__ float sm[];
    float* AsH  = sm + ASH_OFF;
    float* AsL  = sm + ASL_OFF;
    float* BtH  = sm + BTH_OFF;
    float* BtL  = sm + BTL_OFF;
    float* SW   = sm + SW_OFF;
    float* SB   = sm + SB_OFF;
    float* PG   = sm + PG_OFF;
    float* Wsm  = sm + WSM_OFF;
    float* NUM  = sm + NUM_OFF;
    float* DEN  = sm + DEN_OFF;
    float* PRJ  = sm + PRJ_OFF;
    int*   lbl  = (int*)(sm + LBL_OFF);

    const int b    = blockIdx.x;
    const int tid  = threadIdx.x;
    const int lane = tid & 31;
    const int wid  = tid >> 5;
    const int warpM = (wid & 3) * 32;
    const int warpN = (wid >> 2) * 64;
    const int qr = lane >> 2;
    const int qc = lane & 3;

    for (int i = tid; i < 512; i += 256) {
        SW[i] = B_w[i]; SW[512 + i] = Dm_w[i]; SW[1024 + i] = G_w[i];
    }
    if (tid < 12) {
        int p = tid >> 2, l = tid & 3;
        SB[tid] = (p == 0) ? B_b[l] : ((p == 1) ? Dm_b[l] : G_b[l]);
        DEN[tid] = 0.f;
    }
    PG[tid] = g_PG[tid >> 7][b][tid & 127];
    for (int i = tid; i < 1536; i += 256) NUM[i] = 0.f;
    __syncthreads();

    for (int mt = 0; mt < 2; mt++) {
        const int rowbase = b*NPG + mt*128;
        if (tid < 128) {
            lbl[tid]       = t_label[rowbase + tid];
            lbl[128 + tid] = hst[rowbase + tid];
            lbl[256 + tid] = tst[rowbase + tid];
        }
        __syncthreads();

        for (int j = 0; j < 3; j++) {
            float acc[2][8][4];
            #pragma unroll
            for (int mi = 0; mi < 2; mi++)
                #pragma unroll
                for (int ni = 0; ni < 8; ni++)
                    #pragma unroll
                    for (int q = 0; q < 4; q++) acc[mi][ni][q] = 0.f;

            for (int c = 0; c < 16; c++) {
                __syncthreads();
                // A tile: 128 x 32 fp32 -> tf32 hi + lo, k-permuted
                #pragma unroll
                for (int r = 0; r < 4; r++) {
                    int e = r*256 + tid;
                    int m = e >> 3, q = e & 7;
                    float4 v = *(const float4*)(flat + (size_t)(rowbase + m)*512 + c*32 + q*4);
                    int base = m*36 + (q >> 1)*8 + (q & 1);
                    uint32_t hx = f2tf(v.x), hy = f2tf(v.y), hz = f2tf(v.z), hw = f2tf(v.w);
                    AsH[base + 0] = __uint_as_float(hx);
                    AsH[base + 2] = __uint_as_float(hy);
                    AsH[base + 4] = __uint_as_float(hz);
                    AsH[base + 6] = __uint_as_float(hw);
                    AsL[base + 0] = __uint_as_float(f2tf(v.x - __uint_as_float(hx)));
                    AsL[base + 2] = __uint_as_float(f2tf(v.y - __uint_as_float(hy)));
                    AsL[base + 4] = __uint_as_float(f2tf(v.z - __uint_as_float(hz)));
                    AsL[base + 6] = __uint_as_float(f2tf(v.w - __uint_as_float(hw)));
                }
                // B tiles: straight copies of pre-permuted tf32 hi/lo weights
                {
                    const uint32_t* srcH = g_Wt_hi + (size_t)j*65536 + c*32;
                    const uint32_t* srcL = g_Wt_lo + (size_t)j*65536 + c*32;
                    #pragma unroll
                    for (int r = 0; r < 4; r++) {
                        int e = r*256 + tid;
                        int n = e >> 3, q = e & 7;
                        *(float4*)&BtH[n*36 + q*4] = *(const float4*)(srcH + (size_t)n*512 + q*4);
                        *(float4*)&BtL[n*36 + q*4] = *(const float4*)(srcL + (size_t)n*512 + q*4);
                    }
                }
                __syncthreads();
                #pragma unroll
                for (int ks = 0; ks < 4; ks++) {
                    uint32_t ah[2][4], al[2][4], bb[8][2];
                    #pragma unroll
                    for (int mi = 0; mi < 2; mi++) {
                        int row = warpM + mi*16 + qr;
                        float2 h0 = *(const float2*)&AsH[row*36 + ks*8 + qc*2];
                        float2 h1 = *(const float2*)&AsH[(row + 8)*36 + ks*8 + qc*2];
                        ah[mi][0] = __float_as_uint(h0.x); ah[mi][1] = __float_as_uint(h1.x);
                        ah[mi][2] = __float_as_uint(h0.y); ah[mi][3] = __float_as_uint(h1.y);
                        float2 l0 = *(const float2*)&AsL[row*36 + ks*8 + qc*2];
                        float2 l1 = *(const float2*)&AsL[(row + 8)*36 + ks*8 + qc*2];
                        al[mi][0] = __float_as_uint(l0.x); al[mi][1] = __float_as_uint(l1.x);
                        al[mi][2] = __float_as_uint(l0.y); al[mi][3] = __float_as_uint(l1.y);
                    }
                    // pass 1+2: b_hi with a_hi and a_lo
                    #pragma unroll
                    for (int ni = 0; ni < 8; ni++) {
                        int coln = warpN + ni*8 + qr;
                        float2 t = *(const float2*)&BtH[coln*36 + ks*8 + qc*2];
                        bb[ni][0] = __float_as_uint(t.x); bb[ni][1] = __float_as_uint(t.y);
                    }
                    #pragma unroll
                    for (int mi = 0; mi < 2; mi++)
                        #pragma unroll
                        for (int ni = 0; ni < 8; ni++) {
                            mma_tf32(acc[mi][ni], ah[mi], bb[ni]);
                            mma_tf32(acc[mi][ni], al[mi], bb[ni]);
                        }
                    // pass 3: b_lo with a_hi
                    #pragma unroll
                    for (int ni = 0; ni < 8; ni++) {
                        int coln = warpN + ni*8 + qr;
                        float2 t = *(const float2*)&BtL[coln*36 + ks*8 + qc*2];
                        bb[ni][0] = __float_as_uint(t.x); bb[ni][1] = __float_as_uint(t.y);
                    }
                    #pragma unroll
                    for (int mi = 0; mi < 2; mi++)
                        #pragma unroll
                        for (int ni = 0; ni < 8; ni++)
                            mma_tf32(acc[mi][ni], ah[mi], bb[ni]);
                }
            }
            __syncthreads();
            // init per-row projection accumulators with bias (ALL 512 entries)
            {
                float bv = SB[j*4 + (tid & 3)];
                PRJ[tid]       = bv;
                PRJ[tid + 256] = bv;
            }
            __syncthreads();

            // epilogue: adds + ReLU + partial [*,4] projection, in registers
            #pragma unroll
            for (int mi = 0; mi < 2; mi++) {
                #pragma unroll
                for (int h = 0; h < 2; h++) {
                    int r = warpM + mi*16 + qr + h*8;
                    int lT = lbl[r], lH = lbl[128 + r], lS = lbl[256 + r];
                    float p0 = 0.f, p1 = 0.f, p2 = 0.f, p3 = 0.f;
                    #pragma unroll
                    for (int ni = 0; ni < 8; ni++) {
                        int col = warpN + ni*8 + qc*2;
                        float v0 = acc[mi][ni][h*2], v1 = acc[mi][ni][h*2 + 1];
                        float add0, add1;
                        if (j == 0) {
                            float2 t = *(const float2*)&g_tables[0][lT][col];
                            add0 = t.x; add1 = t.y;
                        } else if (j == 1) {
                            float2 t1 = *(const float2*)&g_tables[1][lH][col];
                            float2 t2 = *(const float2*)&g_tables[2][lT][col];
                            add0 = PG[col] + t1.x + t2.x;
                            add1 = PG[col + 1] + t1.y + t2.y;
                        } else {
                            float2 t1 = *(const float2*)&g_tables[3][lS][col];
                            float2 t2 = *(const float2*)&g_tables[4][lT][col];
                            add0 = PG[128 + col] + t1.x + t2.x;
                            add1 = PG[128 + col + 1] + t1.y + t2.y;
                        }
                        float H0 = fmaxf(v0 + add0, 0.f);
                        float H1 = fmaxf(v1 + add1, 0.f);
                        const float* w = SW + j*512 + col*4;
                        p0 += H0*w[0] + H1*w[4];
                        p1 += H0*w[1] + H1*w[5];
                        p2 += H0*w[2] + H1*w[6];
                        p3 += H0*w[3] + H1*w[7];
                    }
                    p0 += __shfl_xor_sync(0xffffffffu, p0, 1);
                    p0 += __shfl_xor_sync(0xffffffffu, p0, 2);
                    p1 += __shfl_xor_sync(0xffffffffu, p1, 1);
                    p1 += __shfl_xor_sync(0xffffffffu, p1, 2);
                    p2 += __shfl_xor_sync(0xffffffffu, p2, 1);
                    p2 += __shfl_xor_sync(0xffffffffu, p2, 2);
                    p3 += __shfl_xor_sync(0xffffffffu, p3, 1);
                    p3 += __shfl_xor_sync(0xffffffffu, p3, 2);
                    float pl = (qc == 0) ? p0 : ((qc == 1) ? p1 : ((qc == 2) ? p2 : p3));
                    atomicAdd(&PRJ[r*4 + qc], pl);
                }
            }
            __syncthreads();
            if (tid < 128) {
                int m = tid;
                float g0 = 1.f/(1.f + expf(-PRJ[m*4 + 0]));
                float g1 = 1.f/(1.f + expf(-PRJ[m*4 + 1]));
                float g2 = 1.f/(1.f + expf(-PRJ[m*4 + 2]));
                float g3 = 1.f/(1.f + expf(-PRJ[m*4 + 3]));
                if (j == 1) {
                    const float* hsv = head_sister + (size_t)(rowbase + m)*4;
                    g0 *= hsv[0]; g1 *= hsv[1]; g2 *= hsv[2]; g3 *= hsv[3];
                } else if (j == 2) {
                    const float* tsv = tail_sister + (size_t)(rowbase + m)*4;
                    g0 *= tsv[0]; g1 *= tsv[1]; g2 *= tsv[2]; g3 *= tsv[3];
                }
                float* wp = Wsm + (size_t)(j*128 + m)*4;
                wp[0] = g0; wp[1] = g1; wp[2] = g2; wp[3] = g3;
            }
            __syncthreads();
        }

        // weighted segment sums for this tile
        {
            int c0 = tid, c1 = tid + 256;
            int l0 = tid >> 7, l1 = l0 + 2;
            float s00=0,s01=0,s02=0, s10=0,s11=0,s12=0;
            for (int n = 0; n < 128; n++) {
                float v0 = flat[(size_t)(rowbase + n)*512 + c0];
                float v1 = flat[(size_t)(rowbase + n)*512 + c1];
                float w0 = Wsm[(0*128+n)*4 + l0], w1 = Wsm[(1*128+n)*4 + l0], w2 = Wsm[(2*128+n)*4 + l0];
                float x0 = Wsm[(0*128+n)*4 + l1], x1 = Wsm[(1*128+n)*4 + l1], x2 = Wsm[(2*128+n)*4 + l1];
                s00 += w0*v0; s01 += w1*v0; s02 += w2*v0;
                s10 += x0*v1; s11 += x1*v1; s12 += x2*v1;
            }
            NUM[0*512 + c0] += s00; NUM[1*512 + c0] += s01; NUM[2*512 + c0] += s02;
            NUM[0*512 + c1] += s10; NUM[1*512 + c1] += s11; NUM[2*512 + c1] += s12;
            if (tid < 12) {
                int p = tid >> 2, l = tid & 3;
                float s = 0.f;
                for (int n = 0; n < 128; n++) s += Wsm[(p*128 + n)*4 + l];
                DEN[tid] += s;
            }
        }
        __syncthreads();
    }

    {
        int c0 = tid, c1 = tid + 256;
        int l0 = tid >> 7, l1 = l0 + 2;
        #pragma unroll
        for (int p = 0; p < 3; p++) {
            g_gsum[b][p][c0] = NUM[p*512 + c0] / DEN[p*4 + l0];
            g_gsum[b][p][c1] = NUM[p*512 + c1] / DEN[p*4 + l1];
        }
    }
}

// ---------------- kernel 3.5: assemble g_ht rows ------------------------
__global__ void k_ght(const float* __restrict__ flat,
                      const int* __restrict__ head_ids, const int* __restrict__ tail_ids,
                      const int* __restrict__ rel_labels,
                      const float* __restrict__ she, const float* __restrict__ ste)
{
    int b = blockIdx.x, tid = threadIdx.x;
    int h = head_ids[b], t = tail_ids[b];
    float* out = g_ght[b];
    for (int c = tid; c < 512; c += 256) {
        float ghs = g_gsum[b][1][c], gts = g_gsum[b][2][c];
        float hv = flat[(size_t)h*512 + c], tv = flat[(size_t)t*512 + c];
        out[c]        = ghs * hv;
        out[512 + c]  = gts * tv;
        out[1024 + c] = ghs;
        out[1536 + c] = gts;
        out[2048 + c] = hv;
        out[2560 + c] = tv;
    }
    if (tid < 64) {
        int r = rel_labels[b];
        out[3072 + tid] = she[r*64 + tid];
        out[3136 + tid] = ste[r*64 + tid];
    }
}

// ---------------- kernel 4a: ht GEMM split-K (partials) -----------------
__global__ __launch_bounds__(256) void k_ht(const float* __restrict__ ht_w)
{
    __shared__ float As2[64][33], Bs2[32][65];
    int m0 = blockIdx.y*64, n0 = blockIdx.x*64, kbase = blockIdx.z*800;
    int tid = threadIdx.x, tx = tid & 15, ty = tid >> 4;
    float acc[4][4] = {};
    for (int kc = 0; kc < 25; kc++) {
        int k0 = kbase + kc*32;
        #pragma unroll
        for (int r = 0; r < 8; r++) {
            int e = r*256 + tid; int m = e >> 5, k = e & 31;
            As2[m][k] = g_ght[m0 + m][k0 + k];
        }
        #pragma unroll
        for (int r = 0; r < 8; r++) {
            int e = r*256 + tid; int k = e >> 6, n = e & 63;
            Bs2[k][n] = ht_w[(size_t)(k0 + k)*512 + n0 + n];
        }
        __syncthreads();
        #pragma unroll
        for (int k = 0; k < 32; k++) {
            float a[4], bv[4];
            #pragma unroll
            for (int i = 0; i < 4; i++) { a[i] = As2[ty*4 + i][k]; bv[i] = Bs2[k][tx*4 + i]; }
            #pragma unroll
            for (int i = 0; i < 4; i++)
                #pragma unroll
                for (int q = 0; q < 4; q++) acc[i][q] += a[i]*bv[q];
        }
        __syncthreads();
    }
    #pragma unroll
    for (int i = 0; i < 4; i++)
        #pragma unroll
        for (int q = 0; q < 4; q++)
            g_htacc[blockIdx.z][m0 + ty*4 + i][n0 + tx*4 + q] = acc[i][q];
}

// ---------------- kernel 4b: fc + out -----------------------------------
__global__ void k_final(const float* __restrict__ flat,
                        const int* __restrict__ head_ids, const int* __restrict__ tail_ids,
                        const int* __restrict__ rel_labels, const float* __restrict__ rel_emb,
                        const float* __restrict__ ht_b,
                        const float* __restrict__ fc_w, const float* __restrict__ fc_b,
                        const float* __restrict__ out_w, const float* __restrict__ out_b,
                        float* __restrict__ out)
{
    __shared__ float rep[2112];
    __shared__ float red[256][17];
    int b = blockIdx.x, tid = threadIdx.x;
    int h = head_ids[b], t = tail_ids[b];
    for (int c = tid; c < 512; c += 256) {
        rep[c]        = g_gsum[b][0][c];
        rep[512 + c]  = flat[(size_t)h*512 + c];
        rep[1024 + c] = flat[(size_t)t*512 + c];
        float s = g_htacc[0][b][c] + g_htacc[1][b][c] + g_htacc[2][b][c] + g_htacc[3][b][c];
        rep[1536 + c] = fmaxf(s + ht_b[c], 0.f);
    }
    if (tid < 64) rep[2048 + tid] = rel_emb[rel_labels[b]*64 + tid];
    __syncthreads();

    float acc[16];
    #pragma unroll
    for (int j = 0; j < 16; j++) acc[j] = 0.f;
    for (int k = tid; k < 2112; k += 256) {
        float x = rep[k];
        const float4* w = (const float4*)(fc_w + (size_t)k*16);
        #pragma unroll
        for (int v = 0; v < 4; v++) {
            float4 ww = w[v];
            acc[v*4+0] += x*ww.x; acc[v*4+1] += x*ww.y;
            acc[v*4+2] += x*ww.z; acc[v*4+3] += x*ww.w;
        }
    }
    #pragma unroll
    for (int j = 0; j < 16; j++) red[tid][j] = acc[j];
    __syncthreads();
    for (int s = 128; s >= 1; s >>= 1) {
        if (tid < s) {
            #pragma unroll
            for (int j = 0; j < 16; j++) red[tid][j] += red[tid + s][j];
        }
        __syncthreads();
    }
    if (tid == 0) {
        float o = out_b[0];
        #pragma unroll
        for (int j = 0; j < 16; j++) o += fmaxf(red[0][j] + fc_b[j], 0.f) * out_w[j];
        out[b] = o;
    }
}

// ---------------- launch ------------------------------------------------
extern "C" void kernel_launch(void* const* d_in, const int* in_sizes, int n_in,
                              void* d_out, int out_size)
{
    const float* node_repr = (const float*)d_in[0];
    const float* head_sis  = (const float*)d_in[1];
    const float* tail_sis  = (const float*)d_in[2];
    const int*   t_label   = (const int*)d_in[3];
    const int*   hstp      = (const int*)d_in[4];
    const int*   tstp      = (const int*)d_in[5];
    const int*   head_ids  = (const int*)d_in[7];
    const int*   tail_ids  = (const int*)d_in[8];
    const int*   rel_lab   = (const int*)d_in[9];
    const float* rel_emb   = (const float*)d_in[10];
    const float* she       = (const float*)d_in[11];
    const float* ste       = (const float*)d_in[12];
    const float* A_w  = (const float*)d_in[13]; const float* A_b  = (const float*)d_in[14];
    const float* B_w  = (const float*)d_in[15]; const float* B_b  = (const float*)d_in[16];
    const float* C_w  = (const float*)d_in[17]; const float* C_b  = (const float*)d_in[18];
    const float* Dm_w = (const float*)d_in[19]; const float* Dm_b = (const float*)d_in[20];
    const float* E_w  = (const float*)d_in[21]; const float* E_b  = (const float*)d_in[22];
    const float* G_w  = (const float*)d_in[23]; const float* G_b  = (const float*)d_in[24];
    const float* ht_w = (const float*)d_in[25]; const float* ht_b = (const float*)d_in[26];
    const float* fc_w = (const float*)d_in[27]; const float* fc_b = (const float*)d_in[28];
    const float* out_w= (const float*)d_in[29]; const float* out_b= (const float*)d_in[30];
    float* out = (float*)d_out;

    const int smemBytes = SM_FLOATS * 4;
    cudaFuncSetAttribute(k_fused_mma, cudaFuncAttributeMaxDynamicSharedMemorySize, smemBytes);

    k_tables<<<dim3(Rr, 5), 128>>>(rel_emb, she, ste, A_w, A_b, C_w, C_b, E_w, E_b);
    k_prep<<<dim3(16, 3), 256>>>(A_w, C_w, E_w);
    k_pg<<<dim3(4, 16, 2), 256>>>(node_repr, head_ids, tail_ids, C_w, E_w);
    k_fused_mma<<<Bg, 256, smemBytes>>>(node_repr, head_sis, tail_sis, t_label, hstp, tstp,
                                        B_w, B_b, Dm_w, Dm_b, G_w, G_b);
    k_ght<<<Bg, 256>>>(node_repr, head_ids, tail_ids, rel_lab, she, ste);
    k_ht<<<dim3(8, 8, 4), 256>>>(ht_w);
    k_final<<<Bg, 256>>>(node_repr, head_ids, tail_ids, rel_lab, rel_emb, ht_b,
                         fc_w, fc_b, out_w, out_b, out);
}